// round 3
// baseline (speedup 1.0000x reference)
#include <cuda_runtime.h>
#include <cuda_bf16.h>
#include <cstdint>

#define N_NODES 50000
#define OUT_DIM 128
#define NNZ_MAX 800000
#define SCAN_T  1024

// ---------------------------------------------------------------------------
// Device-global scratch (no runtime allocation). Referenced only from device
// code; never passed as host-side kernel arguments.
// ---------------------------------------------------------------------------
__device__ float g_xw1[(size_t)N_NODES * OUT_DIM];
__device__ float g_xw2[(size_t)N_NODES * OUT_DIM];

// Per-relation CSR build state. rel: 0=feat, 1=adj1, 2=adj2
__device__ int   g_cnt[3 * N_NODES];          // histogram, then scatter cursors
__device__ int   g_rowptr[3 * (N_NODES + 1)];
__device__ int   g_scol[3 * (size_t)NNZ_MAX]; // row-sorted column indices
__device__ float g_sval[3 * (size_t)NNZ_MAX]; // row-sorted values

// ---------------------------------------------------------------------------
// 1) zero histogram counters
// ---------------------------------------------------------------------------
__global__ void zero_cnt_kernel() {
    int stride = gridDim.x * blockDim.x;
    for (int i = blockIdx.x * blockDim.x + threadIdx.x; i < 3 * N_NODES; i += stride)
        g_cnt[i] = 0;
}

// ---------------------------------------------------------------------------
// 2) histogram of rows for all three relations (int atomics, spread -> fast)
// ---------------------------------------------------------------------------
__global__ void hist_kernel(const int* __restrict__ frow,
                            const int* __restrict__ a1row,
                            const int* __restrict__ a2row,
                            int nf, int n1, int n2) {
    int total  = nf + n1 + n2;
    int stride = gridDim.x * blockDim.x;
    for (int i = blockIdx.x * blockDim.x + threadIdx.x; i < total; i += stride) {
        int rel, r;
        if (i < nf)            { rel = 0; r = frow[i]; }
        else if (i < nf + n1)  { rel = 1; r = a1row[i - nf]; }
        else                   { rel = 2; r = a2row[i - nf - n1]; }
        atomicAdd(&g_cnt[rel * N_NODES + r], 1);
    }
}

// ---------------------------------------------------------------------------
// 3) exclusive scan of each relation's histogram (single block).
//    Writes g_rowptr and resets g_cnt to the row base (scatter cursor).
// ---------------------------------------------------------------------------
__global__ void scan_kernel() {
    __shared__ int sh[SCAN_T];
    const int t = threadIdx.x;
    const int ITEMS = (N_NODES + SCAN_T - 1) / SCAN_T;  // 49

    for (int rel = 0; rel < 3; rel++) {
        int* cnt = g_cnt    + rel * N_NODES;
        int* rp  = g_rowptr + rel * (N_NODES + 1);
        int base = t * ITEMS;

        // per-thread chunk sum
        int sum = 0;
        #pragma unroll 4
        for (int i = 0; i < ITEMS; i++) {
            int idx = base + i;
            if (idx < N_NODES) sum += cnt[idx];
        }
        sh[t] = sum;
        __syncthreads();

        // inclusive Hillis-Steele scan over 1024 partials
        for (int off = 1; off < SCAN_T; off <<= 1) {
            int add = (t >= off) ? sh[t - off] : 0;
            __syncthreads();
            sh[t] += add;
            __syncthreads();
        }

        // write exclusive prefixes; reset cnt to cursor base
        int run = sh[t] - sum;  // exclusive prefix of this thread's chunk
        for (int i = 0; i < ITEMS; i++) {
            int idx = base + i;
            if (idx < N_NODES) {
                int c = cnt[idx];
                rp[idx]  = run;
                cnt[idx] = run;   // cursor
                run += c;
            }
        }
        if (t == SCAN_T - 1) rp[N_NODES] = run;  // total nnz
        __syncthreads();  // sh reused next iteration
    }
}

// ---------------------------------------------------------------------------
// 4) scatter edges into row-sorted arrays
// ---------------------------------------------------------------------------
__global__ void scatter_kernel(const int* __restrict__ frow, const int* __restrict__ fcol,
                               const float* __restrict__ fval,
                               const int* __restrict__ a1row, const int* __restrict__ a1col,
                               const float* __restrict__ a1val,
                               const int* __restrict__ a2row, const int* __restrict__ a2col,
                               const float* __restrict__ a2val,
                               int nf, int n1, int n2) {
    int total  = nf + n1 + n2;
    int stride = gridDim.x * blockDim.x;
    for (int i = blockIdx.x * blockDim.x + threadIdx.x; i < total; i += stride) {
        int rel, r, c; float v;
        if (i < nf) {
            rel = 0; int e = i;
            r = frow[e]; c = fcol[e]; v = fval[e];
        } else if (i < nf + n1) {
            rel = 1; int e = i - nf;
            r = a1row[e]; c = a1col[e]; v = a1val[e];
        } else {
            rel = 2; int e = i - nf - n1;
            r = a2row[e]; c = a2col[e]; v = a2val[e];
        }
        int pos = atomicAdd(&g_cnt[rel * N_NODES + r], 1);
        size_t o = (size_t)rel * NNZ_MAX + pos;
        g_scol[o] = c;
        g_sval[o] = v;
    }
}

// ---------------------------------------------------------------------------
// 5) feature SpMM, CSR form: one warp per node.
//    g_xw1[r] = sum v*W1[c] ; g_xw2[r] = sum v*W2[c]. Plain stores, no atomics.
//    Rows with no features get zeros (replaces scratch zeroing).
// ---------------------------------------------------------------------------
__global__ void feat_csr_kernel(const float* __restrict__ W1,
                                const float* __restrict__ W2) {
    int r    = (blockIdx.x * blockDim.x + threadIdx.x) >> 5;
    int lane = threadIdx.x & 31;
    if (r >= N_NODES) return;

    const int* rp = g_rowptr;  // rel 0
    int s = rp[r], e = rp[r + 1];

    float4 acc1 = make_float4(0.f, 0.f, 0.f, 0.f);
    float4 acc2 = make_float4(0.f, 0.f, 0.f, 0.f);

    for (int i = s; i < e; i++) {
        int   c = g_scol[i];
        float v = g_sval[i];
        float4 w1 = reinterpret_cast<const float4*>(W1 + (size_t)c * OUT_DIM)[lane];
        float4 w2 = reinterpret_cast<const float4*>(W2 + (size_t)c * OUT_DIM)[lane];
        acc1.x += v * w1.x; acc1.y += v * w1.y; acc1.z += v * w1.z; acc1.w += v * w1.w;
        acc2.x += v * w2.x; acc2.y += v * w2.y; acc2.z += v * w2.z; acc2.w += v * w2.w;
    }
    reinterpret_cast<float4*>(g_xw1 + (size_t)r * OUT_DIM)[lane] = acc1;
    reinterpret_cast<float4*>(g_xw2 + (size_t)r * OUT_DIM)[lane] = acc2;
}

// ---------------------------------------------------------------------------
// 6) adjacency SpMM (both relations) + relu, CSR form: one warp per node.
//    out[r] = relu( sum_{e in adj1[r]} v*xw1[c]  +  sum_{e in adj2[r]} v*xw2[c] )
// ---------------------------------------------------------------------------
__global__ void adj_relu_kernel(float* __restrict__ out) {
    int r    = (blockIdx.x * blockDim.x + threadIdx.x) >> 5;
    int lane = threadIdx.x & 31;
    if (r >= N_NODES) return;

    float4 acc = make_float4(0.f, 0.f, 0.f, 0.f);

    // relation 1
    {
        const int* rp = g_rowptr + 1 * (N_NODES + 1);
        int s = rp[r], e = rp[r + 1];
        const int*   scol = g_scol + 1 * (size_t)NNZ_MAX;
        const float* sval = g_sval + 1 * (size_t)NNZ_MAX;
        for (int i = s; i < e; i++) {
            int   c = scol[i];
            float v = sval[i];
            float4 h = reinterpret_cast<const float4*>(g_xw1 + (size_t)c * OUT_DIM)[lane];
            acc.x += v * h.x; acc.y += v * h.y; acc.z += v * h.z; acc.w += v * h.w;
        }
    }
    // relation 2
    {
        const int* rp = g_rowptr + 2 * (N_NODES + 1);
        int s = rp[r], e = rp[r + 1];
        const int*   scol = g_scol + 2 * (size_t)NNZ_MAX;
        const float* sval = g_sval + 2 * (size_t)NNZ_MAX;
        for (int i = s; i < e; i++) {
            int   c = scol[i];
            float v = sval[i];
            float4 h = reinterpret_cast<const float4*>(g_xw2 + (size_t)c * OUT_DIM)[lane];
            acc.x += v * h.x; acc.y += v * h.y; acc.z += v * h.z; acc.w += v * h.w;
        }
    }

    acc.x = fmaxf(acc.x, 0.f);
    acc.y = fmaxf(acc.y, 0.f);
    acc.z = fmaxf(acc.z, 0.f);
    acc.w = fmaxf(acc.w, 0.f);
    reinterpret_cast<float4*>(out + (size_t)r * OUT_DIM)[lane] = acc;
}

// ---------------------------------------------------------------------------
// Launch. Input order: feat_row, feat_col, feat_vals, adj1_row, adj1_col,
// adj1_vals, adj2_row, adj2_col, adj2_vals, W1, W2, n_nodes
// ---------------------------------------------------------------------------
extern "C" void kernel_launch(void* const* d_in, const int* in_sizes, int n_in,
                              void* d_out, int out_size) {
    const int*   feat_row = (const int*)  d_in[0];
    const int*   feat_col = (const int*)  d_in[1];
    const float* feat_val = (const float*)d_in[2];
    const int*   a1_row   = (const int*)  d_in[3];
    const int*   a1_col   = (const int*)  d_in[4];
    const float* a1_val   = (const float*)d_in[5];
    const int*   a2_row   = (const int*)  d_in[6];
    const int*   a2_col   = (const int*)  d_in[7];
    const float* a2_val   = (const float*)d_in[8];
    const float* W1       = (const float*)d_in[9];
    const float* W2       = (const float*)d_in[10];
    float* out = (float*)d_out;

    const int nf = in_sizes[0];
    const int n1 = in_sizes[3];
    const int n2 = in_sizes[6];
    const int total_edges = nf + n1 + n2;

    // CSR build
    zero_cnt_kernel<<<256, 256>>>();
    hist_kernel<<<(total_edges + 255) / 256, 256>>>(feat_row, a1_row, a2_row, nf, n1, n2);
    scan_kernel<<<1, SCAN_T>>>();
    scatter_kernel<<<(total_edges + 255) / 256, 256>>>(feat_row, feat_col, feat_val,
                                                       a1_row, a1_col, a1_val,
                                                       a2_row, a2_col, a2_val,
                                                       nf, n1, n2);

    // SpMMs: one warp per node (8 warps per 256-thread block)
    const int node_blocks = (N_NODES + 7) / 8;
    feat_csr_kernel<<<node_blocks, 256>>>(W1, W2);
    adj_relu_kernel<<<node_blocks, 256>>>(out);
}

// round 4
// speedup vs baseline: 2.3279x; 2.3279x over previous
#include <cuda_runtime.h>
#include <cuda_bf16.h>
#include <cstdint>

#define N_NODES    50000
#define OUT_DIM    128
#define NNZ_MAX    800000
#define NB_PER_REL 196                     // ceil(50000/256) blocks per relation
#define NPB        256                     // nodes per scan block

// ---------------------------------------------------------------------------
// Device-global scratch (no runtime allocation). Referenced only from device
// code; never passed as host-side kernel arguments.
// ---------------------------------------------------------------------------
__device__ float g_xw1[(size_t)N_NODES * OUT_DIM];
__device__ float g_xw2[(size_t)N_NODES * OUT_DIM];

// Per-relation CSR build state. rel: 0=feat, 1=adj1, 2=adj2
__device__ int  g_cnt[3 * N_NODES];            // histogram -> scatter cursors
__device__ int  g_rowptr[3 * (N_NODES + 1)];   // also temp for block-local scan
__device__ int  g_blocksum[3 * NB_PER_REL];
__device__ int2 g_pack[3 * (size_t)NNZ_MAX];   // row-sorted {col, val_bits}

// ---------------------------------------------------------------------------
// 1) zero histogram counters
// ---------------------------------------------------------------------------
__global__ void zero_cnt_kernel() {
    int stride = gridDim.x * blockDim.x;
    for (int i = blockIdx.x * blockDim.x + threadIdx.x; i < 3 * N_NODES; i += stride)
        g_cnt[i] = 0;
}

// ---------------------------------------------------------------------------
// 2) histogram of rows (spread int atomics -> cheap)
// ---------------------------------------------------------------------------
__global__ void hist_kernel(const int* __restrict__ frow,
                            const int* __restrict__ a1row,
                            const int* __restrict__ a2row,
                            int nf, int n1, int n2) {
    int total  = nf + n1 + n2;
    int stride = gridDim.x * blockDim.x;
    for (int i = blockIdx.x * blockDim.x + threadIdx.x; i < total; i += stride) {
        int rel, r;
        if (i < nf)           { rel = 0; r = frow[i]; }
        else if (i < nf + n1) { rel = 1; r = a1row[i - nf]; }
        else                  { rel = 2; r = a2row[i - nf - n1]; }
        atomicAdd(&g_cnt[rel * N_NODES + r], 1);
    }
}

// ---------------------------------------------------------------------------
// 3a) block-local exclusive scan of counts; block sums to g_blocksum.
//     Exclusive-in-block values parked in g_rowptr (temp).
// ---------------------------------------------------------------------------
__global__ void scanA_kernel() {
    __shared__ int sh[NPB];
    int rel = blockIdx.x / NB_PER_REL;
    int blk = blockIdx.x % NB_PER_REL;
    int idx = blk * NPB + threadIdx.x;

    int v = (idx < N_NODES) ? g_cnt[rel * N_NODES + idx] : 0;
    sh[threadIdx.x] = v;
    __syncthreads();
    for (int off = 1; off < NPB; off <<= 1) {
        int add = (threadIdx.x >= off) ? sh[threadIdx.x - off] : 0;
        __syncthreads();
        sh[threadIdx.x] += add;
        __syncthreads();
    }
    if (idx < N_NODES)
        g_rowptr[rel * (N_NODES + 1) + idx] = sh[threadIdx.x] - v;  // exclusive
    if (threadIdx.x == NPB - 1)
        g_blocksum[rel * NB_PER_REL + blk] = sh[NPB - 1];           // block total
}

// ---------------------------------------------------------------------------
// 3b) scan the 196 block sums within each relation (one block).
// ---------------------------------------------------------------------------
__global__ void scanB_kernel() {
    __shared__ int sh[3 * NB_PER_REL];
    int t = threadIdx.x;                       // blockDim = 1024
    if (t < 3 * NB_PER_REL) sh[t] = g_blocksum[t];
    __syncthreads();
    int seg_pos = t % NB_PER_REL;
    for (int off = 1; off < NB_PER_REL; off <<= 1) {
        int add = 0;
        if (t < 3 * NB_PER_REL && seg_pos >= off) add = sh[t - off];
        __syncthreads();
        if (t < 3 * NB_PER_REL) sh[t] += add;
        __syncthreads();
    }
    if (t < 3 * NB_PER_REL) g_blocksum[t] = sh[t];  // inclusive per relation
}

// ---------------------------------------------------------------------------
// 3c) apply block offsets: finalize rowptr, init cursors, write totals.
// ---------------------------------------------------------------------------
__global__ void scanC_kernel() {
    int rel = blockIdx.x / NB_PER_REL;
    int blk = blockIdx.x % NB_PER_REL;
    int idx = blk * NPB + threadIdx.x;
    if (idx >= N_NODES) return;

    int off  = blk ? g_blocksum[rel * NB_PER_REL + blk - 1] : 0;
    int excl = g_rowptr[rel * (N_NODES + 1) + idx] + off;
    int orig = g_cnt[rel * N_NODES + idx];

    g_rowptr[rel * (N_NODES + 1) + idx] = excl;
    g_cnt[rel * N_NODES + idx]          = excl;   // scatter cursor
    if (idx == N_NODES - 1)
        g_rowptr[rel * (N_NODES + 1) + N_NODES] = excl + orig;
}

// ---------------------------------------------------------------------------
// 4) scatter edges into row-sorted packed arrays (one 8B store per edge)
// ---------------------------------------------------------------------------
__global__ void scatter_kernel(const int* __restrict__ frow, const int* __restrict__ fcol,
                               const float* __restrict__ fval,
                               const int* __restrict__ a1row, const int* __restrict__ a1col,
                               const float* __restrict__ a1val,
                               const int* __restrict__ a2row, const int* __restrict__ a2col,
                               const float* __restrict__ a2val,
                               int nf, int n1, int n2) {
    int total  = nf + n1 + n2;
    int stride = gridDim.x * blockDim.x;
    for (int i = blockIdx.x * blockDim.x + threadIdx.x; i < total; i += stride) {
        int rel, r, c; float v;
        if (i < nf) {
            rel = 0; r = frow[i]; c = fcol[i]; v = fval[i];
        } else if (i < nf + n1) {
            int e = i - nf;
            rel = 1; r = a1row[e]; c = a1col[e]; v = a1val[e];
        } else {
            int e = i - nf - n1;
            rel = 2; r = a2row[e]; c = a2col[e]; v = a2val[e];
        }
        int pos = atomicAdd(&g_cnt[rel * N_NODES + r], 1);
        g_pack[(size_t)rel * NNZ_MAX + pos] = make_int2(c, __float_as_int(v));
    }
}

// ---------------------------------------------------------------------------
// 5) feature SpMM, CSR: one warp per node, unroll-4 for MLP. Plain stores.
// ---------------------------------------------------------------------------
__device__ __forceinline__ void fma4(float4& a, float v, const float4& w) {
    a.x += v * w.x; a.y += v * w.y; a.z += v * w.z; a.w += v * w.w;
}

__global__ void feat_csr_kernel(const float* __restrict__ W1,
                                const float* __restrict__ W2) {
    int r    = (blockIdx.x * blockDim.x + threadIdx.x) >> 5;
    int lane = threadIdx.x & 31;
    if (r >= N_NODES) return;

    int s = g_rowptr[r], e = g_rowptr[r + 1];
    const int2* pk = g_pack;  // rel 0

    float4 acc1 = make_float4(0.f, 0.f, 0.f, 0.f);
    float4 acc2 = make_float4(0.f, 0.f, 0.f, 0.f);

    int i = s;
    for (; i + 4 <= e; i += 4) {
        int2 p0 = pk[i], p1 = pk[i + 1], p2 = pk[i + 2], p3 = pk[i + 3];
        float4 a0 = reinterpret_cast<const float4*>(W1 + (size_t)p0.x * OUT_DIM)[lane];
        float4 b0 = reinterpret_cast<const float4*>(W2 + (size_t)p0.x * OUT_DIM)[lane];
        float4 a1 = reinterpret_cast<const float4*>(W1 + (size_t)p1.x * OUT_DIM)[lane];
        float4 b1 = reinterpret_cast<const float4*>(W2 + (size_t)p1.x * OUT_DIM)[lane];
        float4 a2 = reinterpret_cast<const float4*>(W1 + (size_t)p2.x * OUT_DIM)[lane];
        float4 b2 = reinterpret_cast<const float4*>(W2 + (size_t)p2.x * OUT_DIM)[lane];
        float4 a3 = reinterpret_cast<const float4*>(W1 + (size_t)p3.x * OUT_DIM)[lane];
        float4 b3 = reinterpret_cast<const float4*>(W2 + (size_t)p3.x * OUT_DIM)[lane];
        fma4(acc1, __int_as_float(p0.y), a0); fma4(acc2, __int_as_float(p0.y), b0);
        fma4(acc1, __int_as_float(p1.y), a1); fma4(acc2, __int_as_float(p1.y), b1);
        fma4(acc1, __int_as_float(p2.y), a2); fma4(acc2, __int_as_float(p2.y), b2);
        fma4(acc1, __int_as_float(p3.y), a3); fma4(acc2, __int_as_float(p3.y), b3);
    }
    for (; i < e; i++) {
        int2 p = pk[i];
        float v = __int_as_float(p.y);
        float4 w1 = reinterpret_cast<const float4*>(W1 + (size_t)p.x * OUT_DIM)[lane];
        float4 w2 = reinterpret_cast<const float4*>(W2 + (size_t)p.x * OUT_DIM)[lane];
        fma4(acc1, v, w1);
        fma4(acc2, v, w2);
    }
    reinterpret_cast<float4*>(g_xw1 + (size_t)r * OUT_DIM)[lane] = acc1;
    reinterpret_cast<float4*>(g_xw2 + (size_t)r * OUT_DIM)[lane] = acc2;
}

// ---------------------------------------------------------------------------
// 6) adjacency SpMM (both relations) + relu: one warp per node, unroll-4.
// ---------------------------------------------------------------------------
template <int REL>
__device__ __forceinline__ void adj_accum(int r, int lane, const float* __restrict__ H,
                                          float4& acc) {
    const int* rp = g_rowptr + REL * (N_NODES + 1);
    int s = rp[r], e = rp[r + 1];
    const int2* pk = g_pack + REL * (size_t)NNZ_MAX;

    int i = s;
    for (; i + 4 <= e; i += 4) {
        int2 p0 = pk[i], p1 = pk[i + 1], p2 = pk[i + 2], p3 = pk[i + 3];
        float4 h0 = reinterpret_cast<const float4*>(H + (size_t)p0.x * OUT_DIM)[lane];
        float4 h1 = reinterpret_cast<const float4*>(H + (size_t)p1.x * OUT_DIM)[lane];
        float4 h2 = reinterpret_cast<const float4*>(H + (size_t)p2.x * OUT_DIM)[lane];
        float4 h3 = reinterpret_cast<const float4*>(H + (size_t)p3.x * OUT_DIM)[lane];
        fma4(acc, __int_as_float(p0.y), h0);
        fma4(acc, __int_as_float(p1.y), h1);
        fma4(acc, __int_as_float(p2.y), h2);
        fma4(acc, __int_as_float(p3.y), h3);
    }
    for (; i < e; i++) {
        int2 p = pk[i];
        float4 h = reinterpret_cast<const float4*>(H + (size_t)p.x * OUT_DIM)[lane];
        fma4(acc, __int_as_float(p.y), h);
    }
}

__global__ void adj_relu_kernel(float* __restrict__ out) {
    int r    = (blockIdx.x * blockDim.x + threadIdx.x) >> 5;
    int lane = threadIdx.x & 31;
    if (r >= N_NODES) return;

    float4 acc = make_float4(0.f, 0.f, 0.f, 0.f);
    adj_accum<1>(r, lane, g_xw1, acc);
    adj_accum<2>(r, lane, g_xw2, acc);

    acc.x = fmaxf(acc.x, 0.f);
    acc.y = fmaxf(acc.y, 0.f);
    acc.z = fmaxf(acc.z, 0.f);
    acc.w = fmaxf(acc.w, 0.f);
    reinterpret_cast<float4*>(out + (size_t)r * OUT_DIM)[lane] = acc;
}

// ---------------------------------------------------------------------------
// Launch. Input order: feat_row, feat_col, feat_vals, adj1_row, adj1_col,
// adj1_vals, adj2_row, adj2_col, adj2_vals, W1, W2, n_nodes
// ---------------------------------------------------------------------------
extern "C" void kernel_launch(void* const* d_in, const int* in_sizes, int n_in,
                              void* d_out, int out_size) {
    const int*   feat_row = (const int*)  d_in[0];
    const int*   feat_col = (const int*)  d_in[1];
    const float* feat_val = (const float*)d_in[2];
    const int*   a1_row   = (const int*)  d_in[3];
    const int*   a1_col   = (const int*)  d_in[4];
    const float* a1_val   = (const float*)d_in[5];
    const int*   a2_row   = (const int*)  d_in[6];
    const int*   a2_col   = (const int*)  d_in[7];
    const float* a2_val   = (const float*)d_in[8];
    const float* W1       = (const float*)d_in[9];
    const float* W2       = (const float*)d_in[10];
    float* out = (float*)d_out;

    const int nf = in_sizes[0];
    const int n1 = in_sizes[3];
    const int n2 = in_sizes[6];
    const int total_edges = nf + n1 + n2;

    // CSR build (fully parallel)
    zero_cnt_kernel<<<256, 256>>>();
    hist_kernel<<<(total_edges + 255) / 256, 256>>>(feat_row, a1_row, a2_row, nf, n1, n2);
    scanA_kernel<<<3 * NB_PER_REL, NPB>>>();
    scanB_kernel<<<1, 1024>>>();
    scanC_kernel<<<3 * NB_PER_REL, NPB>>>();
    scatter_kernel<<<(total_edges + 255) / 256, 256>>>(feat_row, feat_col, feat_val,
                                                       a1_row, a1_col, a1_val,
                                                       a2_row, a2_col, a2_val,
                                                       nf, n1, n2);

    // SpMMs: one warp per node, 8 warps per block
    const int node_blocks = (N_NODES + 7) / 8;
    feat_csr_kernel<<<node_blocks, 256>>>(W1, W2);
    adj_relu_kernel<<<node_blocks, 256>>>(out);
}

// round 5
// speedup vs baseline: 2.7341x; 1.1745x over previous
#include <cuda_runtime.h>
#include <cuda_fp16.h>
#include <cstdint>

#define N_NODES    50000
#define OUT_DIM    128
#define IN_DIM     256
#define NNZ_MAX    800000
#define NB_PER_REL 196                     // ceil(50000/256) blocks per relation
#define NPB        256                     // nodes per scan block

// ---------------------------------------------------------------------------
// Device-global scratch. Referenced only from device code.
// xw1/xw2 stored as fp16: one uint2 = 4 halves = lane's 4 columns (8B).
// ---------------------------------------------------------------------------
__device__ uint2 g_xw1h[(size_t)N_NODES * 32];
__device__ uint2 g_xw2h[(size_t)N_NODES * 32];
__device__ uint2 g_w1h[IN_DIM * 32];           // fp16 copy of W1 [256,128]
__device__ uint2 g_w2h[IN_DIM * 32];

// Per-relation CSR build state. rel: 0=feat, 1=adj1, 2=adj2
__device__ int  g_cnt[3 * N_NODES];            // histogram -> scatter cursors
__device__ int  g_rowptr[3 * (N_NODES + 1)];
__device__ int  g_blocksum[3 * NB_PER_REL];
__device__ int2 g_pack[3 * (size_t)NNZ_MAX];   // row-sorted {col, val_bits}

// ---------------------------------------------------------------------------
// helpers
// ---------------------------------------------------------------------------
__device__ __forceinline__ void fma4(float4& a, float v, const float4& w) {
    a.x += v * w.x; a.y += v * w.y; a.z += v * w.z; a.w += v * w.w;
}
__device__ __forceinline__ float4 h4_to_f4(uint2 u) {
    __half2 h01 = *reinterpret_cast<__half2*>(&u.x);
    __half2 h23 = *reinterpret_cast<__half2*>(&u.y);
    float2 f01 = __half22float2(h01);
    float2 f23 = __half22float2(h23);
    return make_float4(f01.x, f01.y, f23.x, f23.y);
}
__device__ __forceinline__ uint2 f4_to_h4(float4 f) {
    __half2 h01 = __floats2half2_rn(f.x, f.y);
    __half2 h23 = __floats2half2_rn(f.z, f.w);
    uint2 u;
    u.x = *reinterpret_cast<unsigned*>(&h01);
    u.y = *reinterpret_cast<unsigned*>(&h23);
    return u;
}

// ---------------------------------------------------------------------------
// 1) zero histogram counters + convert W1/W2 to fp16 (independent work fused)
// ---------------------------------------------------------------------------
__global__ void prep_kernel(const float* __restrict__ W1,
                            const float* __restrict__ W2) {
    int stride = gridDim.x * blockDim.x;
    int tid = blockIdx.x * blockDim.x + threadIdx.x;
    for (int i = tid; i < 3 * N_NODES; i += stride)
        g_cnt[i] = 0;
    for (int i = tid; i < IN_DIM * 32; i += stride) {
        float4 w1 = reinterpret_cast<const float4*>(W1)[i];
        float4 w2 = reinterpret_cast<const float4*>(W2)[i];
        g_w1h[i] = f4_to_h4(w1);
        g_w2h[i] = f4_to_h4(w2);
    }
}

// ---------------------------------------------------------------------------
// 2) histogram of rows (spread int atomics -> cheap)
// ---------------------------------------------------------------------------
__global__ void hist_kernel(const int* __restrict__ frow,
                            const int* __restrict__ a1row,
                            const int* __restrict__ a2row,
                            int nf, int n1, int n2) {
    int total  = nf + n1 + n2;
    int stride = gridDim.x * blockDim.x;
    for (int i = blockIdx.x * blockDim.x + threadIdx.x; i < total; i += stride) {
        int rel, r;
        if (i < nf)           { rel = 0; r = frow[i]; }
        else if (i < nf + n1) { rel = 1; r = a1row[i - nf]; }
        else                  { rel = 2; r = a2row[i - nf - n1]; }
        atomicAdd(&g_cnt[rel * N_NODES + r], 1);
    }
}

// ---------------------------------------------------------------------------
// 3a) block-local exclusive scan of counts; block sums to g_blocksum.
// ---------------------------------------------------------------------------
__global__ void scanA_kernel() {
    __shared__ int sh[NPB];
    int rel = blockIdx.x / NB_PER_REL;
    int blk = blockIdx.x % NB_PER_REL;
    int idx = blk * NPB + threadIdx.x;

    int v = (idx < N_NODES) ? g_cnt[rel * N_NODES + idx] : 0;
    sh[threadIdx.x] = v;
    __syncthreads();
    for (int off = 1; off < NPB; off <<= 1) {
        int add = (threadIdx.x >= off) ? sh[threadIdx.x - off] : 0;
        __syncthreads();
        sh[threadIdx.x] += add;
        __syncthreads();
    }
    if (idx < N_NODES)
        g_rowptr[rel * (N_NODES + 1) + idx] = sh[threadIdx.x] - v;  // exclusive
    if (threadIdx.x == NPB - 1)
        g_blocksum[rel * NB_PER_REL + blk] = sh[NPB - 1];           // block total
}

// ---------------------------------------------------------------------------
// 3b) scan the 196 block sums per relation: one warp per relation, shfl scan.
// ---------------------------------------------------------------------------
__global__ void scanB_kernel() {
    int w    = threadIdx.x >> 5;   // relation
    int lane = threadIdx.x & 31;
    if (w >= 3) return;
    int* bs = g_blocksum + w * NB_PER_REL;
    int run = 0;
    for (int c = 0; c < NB_PER_REL; c += 32) {
        int idx = c + lane;
        int v = (idx < NB_PER_REL) ? bs[idx] : 0;
        #pragma unroll
        for (int off = 1; off < 32; off <<= 1) {
            int t = __shfl_up_sync(0xffffffff, v, off);
            if (lane >= off) v += t;
        }
        v += run;
        if (idx < NB_PER_REL) bs[idx] = v;           // inclusive
        run = __shfl_sync(0xffffffff, v, 31);
    }
}

// ---------------------------------------------------------------------------
// 3c) apply block offsets: finalize rowptr, init cursors, write totals.
// ---------------------------------------------------------------------------
__global__ void scanC_kernel() {
    int rel = blockIdx.x / NB_PER_REL;
    int blk = blockIdx.x % NB_PER_REL;
    int idx = blk * NPB + threadIdx.x;
    if (idx >= N_NODES) return;

    int off  = blk ? g_blocksum[rel * NB_PER_REL + blk - 1] : 0;
    int excl = g_rowptr[rel * (N_NODES + 1) + idx] + off;
    int orig = g_cnt[rel * N_NODES + idx];

    g_rowptr[rel * (N_NODES + 1) + idx] = excl;
    g_cnt[rel * N_NODES + idx]          = excl;   // scatter cursor
    if (idx == N_NODES - 1)
        g_rowptr[rel * (N_NODES + 1) + N_NODES] = excl + orig;
}

// ---------------------------------------------------------------------------
// 4) scatter edges into row-sorted packed arrays (one 8B store per edge)
// ---------------------------------------------------------------------------
__global__ void scatter_kernel(const int* __restrict__ frow, const int* __restrict__ fcol,
                               const float* __restrict__ fval,
                               const int* __restrict__ a1row, const int* __restrict__ a1col,
                               const float* __restrict__ a1val,
                               const int* __restrict__ a2row, const int* __restrict__ a2col,
                               const float* __restrict__ a2val,
                               int nf, int n1, int n2) {
    int total  = nf + n1 + n2;
    int stride = gridDim.x * blockDim.x;
    for (int i = blockIdx.x * blockDim.x + threadIdx.x; i < total; i += stride) {
        int rel, r, c; float v;
        if (i < nf) {
            rel = 0; r = frow[i]; c = fcol[i]; v = fval[i];
        } else if (i < nf + n1) {
            int e = i - nf;
            rel = 1; r = a1row[e]; c = a1col[e]; v = a1val[e];
        } else {
            int e = i - nf - n1;
            rel = 2; r = a2row[e]; c = a2col[e]; v = a2val[e];
        }
        int pos = atomicAdd(&g_cnt[rel * N_NODES + r], 1);
        g_pack[(size_t)rel * NNZ_MAX + pos] = make_int2(c, __float_as_int(v));
    }
}

// ---------------------------------------------------------------------------
// 5) feature SpMM, CSR: one warp per node, fp16 W gathers, fp32 accumulate,
//    fp16 stores. Unroll-4 for MLP.
// ---------------------------------------------------------------------------
__global__ void feat_csr_kernel() {
    int r    = (blockIdx.x * blockDim.x + threadIdx.x) >> 5;
    int lane = threadIdx.x & 31;
    if (r >= N_NODES) return;

    int s = g_rowptr[r], e = g_rowptr[r + 1];
    const int2* pk = g_pack;  // rel 0

    float4 acc1 = make_float4(0.f, 0.f, 0.f, 0.f);
    float4 acc2 = make_float4(0.f, 0.f, 0.f, 0.f);

    int i = s;
    for (; i + 4 <= e; i += 4) {
        int2 p0 = pk[i], p1 = pk[i + 1], p2 = pk[i + 2], p3 = pk[i + 3];
        uint2 a0 = g_w1h[p0.x * 32 + lane], b0 = g_w2h[p0.x * 32 + lane];
        uint2 a1 = g_w1h[p1.x * 32 + lane], b1 = g_w2h[p1.x * 32 + lane];
        uint2 a2 = g_w1h[p2.x * 32 + lane], b2 = g_w2h[p2.x * 32 + lane];
        uint2 a3 = g_w1h[p3.x * 32 + lane], b3 = g_w2h[p3.x * 32 + lane];
        fma4(acc1, __int_as_float(p0.y), h4_to_f4(a0)); fma4(acc2, __int_as_float(p0.y), h4_to_f4(b0));
        fma4(acc1, __int_as_float(p1.y), h4_to_f4(a1)); fma4(acc2, __int_as_float(p1.y), h4_to_f4(b1));
        fma4(acc1, __int_as_float(p2.y), h4_to_f4(a2)); fma4(acc2, __int_as_float(p2.y), h4_to_f4(b2));
        fma4(acc1, __int_as_float(p3.y), h4_to_f4(a3)); fma4(acc2, __int_as_float(p3.y), h4_to_f4(b3));
    }
    for (; i < e; i++) {
        int2 p = pk[i];
        float v = __int_as_float(p.y);
        fma4(acc1, v, h4_to_f4(g_w1h[p.x * 32 + lane]));
        fma4(acc2, v, h4_to_f4(g_w2h[p.x * 32 + lane]));
    }
    g_xw1h[(size_t)r * 32 + lane] = f4_to_h4(acc1);
    g_xw2h[(size_t)r * 32 + lane] = f4_to_h4(acc2);
}

// ---------------------------------------------------------------------------
// 6) adjacency SpMM (both relations) + relu: one warp per node, unroll-4,
//    fp16 gathers, fp32 accumulate, fp32 output.
// ---------------------------------------------------------------------------
template <int REL>
__device__ __forceinline__ void adj_accum(int r, int lane, const uint2* __restrict__ H,
                                          float4& acc) {
    const int* rp = g_rowptr + REL * (N_NODES + 1);
    int s = rp[r], e = rp[r + 1];
    const int2* pk = g_pack + REL * (size_t)NNZ_MAX;

    int i = s;
    for (; i + 4 <= e; i += 4) {
        int2 p0 = pk[i], p1 = pk[i + 1], p2 = pk[i + 2], p3 = pk[i + 3];
        uint2 h0 = H[(size_t)p0.x * 32 + lane];
        uint2 h1 = H[(size_t)p1.x * 32 + lane];
        uint2 h2 = H[(size_t)p2.x * 32 + lane];
        uint2 h3 = H[(size_t)p3.x * 32 + lane];
        fma4(acc, __int_as_float(p0.y), h4_to_f4(h0));
        fma4(acc, __int_as_float(p1.y), h4_to_f4(h1));
        fma4(acc, __int_as_float(p2.y), h4_to_f4(h2));
        fma4(acc, __int_as_float(p3.y), h4_to_f4(h3));
    }
    for (; i < e; i++) {
        int2 p = pk[i];
        fma4(acc, __int_as_float(p.y), h4_to_f4(H[(size_t)p.x * 32 + lane]));
    }
}

__global__ void adj_relu_kernel(float* __restrict__ out) {
    int r    = (blockIdx.x * blockDim.x + threadIdx.x) >> 5;
    int lane = threadIdx.x & 31;
    if (r >= N_NODES) return;

    float4 acc = make_float4(0.f, 0.f, 0.f, 0.f);
    adj_accum<1>(r, lane, g_xw1h, acc);
    adj_accum<2>(r, lane, g_xw2h, acc);

    acc.x = fmaxf(acc.x, 0.f);
    acc.y = fmaxf(acc.y, 0.f);
    acc.z = fmaxf(acc.z, 0.f);
    acc.w = fmaxf(acc.w, 0.f);
    reinterpret_cast<float4*>(out + (size_t)r * OUT_DIM)[lane] = acc;
}

// ---------------------------------------------------------------------------
// Launch. Input order: feat_row, feat_col, feat_vals, adj1_row, adj1_col,
// adj1_vals, adj2_row, adj2_col, adj2_vals, W1, W2, n_nodes
// ---------------------------------------------------------------------------
extern "C" void kernel_launch(void* const* d_in, const int* in_sizes, int n_in,
                              void* d_out, int out_size) {
    const int*   feat_row = (const int*)  d_in[0];
    const int*   feat_col = (const int*)  d_in[1];
    const float* feat_val = (const float*)d_in[2];
    const int*   a1_row   = (const int*)  d_in[3];
    const int*   a1_col   = (const int*)  d_in[4];
    const float* a1_val   = (const float*)d_in[5];
    const int*   a2_row   = (const int*)  d_in[6];
    const int*   a2_col   = (const int*)  d_in[7];
    const float* a2_val   = (const float*)d_in[8];
    const float* W1       = (const float*)d_in[9];
    const float* W2       = (const float*)d_in[10];
    float* out = (float*)d_out;

    const int nf = in_sizes[0];
    const int n1 = in_sizes[3];
    const int n2 = in_sizes[6];
    const int total_edges = nf + n1 + n2;

    // CSR build (fully parallel) + W fp16 conversion
    prep_kernel<<<256, 256>>>(W1, W2);
    hist_kernel<<<(total_edges + 255) / 256, 256>>>(feat_row, a1_row, a2_row, nf, n1, n2);
    scanA_kernel<<<3 * NB_PER_REL, NPB>>>();
    scanB_kernel<<<1, 96>>>();
    scanC_kernel<<<3 * NB_PER_REL, NPB>>>();
    scatter_kernel<<<(total_edges + 255) / 256, 256>>>(feat_row, feat_col, feat_val,
                                                       a1_row, a1_col, a1_val,
                                                       a2_row, a2_col, a2_val,
                                                       nf, n1, n2);

    // SpMMs: one warp per node, 8 warps per block
    const int node_blocks = (N_NODES + 7) / 8;
    feat_csr_kernel<<<node_blocks, 256>>>();
    adj_relu_kernel<<<node_blocks, 256>>>(out);
}